// round 1
// baseline (speedup 1.0000x reference)
#include <cuda_runtime.h>
#include <math.h>

#define NN 50000
#define NE 400000
#define HID 128
#define MUL1 64
#define FEAT 320
#define TE 64
#define NTHREADS 256

typedef unsigned long long u64;

__device__ __forceinline__ u64 pack2(float a, float b) {
    u64 r; asm("mov.b64 %0, {%1,%2};" : "=l"(r) : "f"(a), "f"(b)); return r;
}
__device__ __forceinline__ void unpack2(u64 v, float& a, float& b) {
    asm("mov.b64 {%0,%1}, %2;" : "=f"(a), "=f"(b) : "l"(v));
}
__device__ __forceinline__ void fma2(u64& d, u64 a, u64 b) {
    asm("fma.rn.f32x2 %0, %1, %2, %0;" : "+l"(d) : "l"(a), "l"(b));
}

// ---------------- zero kernel ----------------
__global__ void zero_kernel(float4* out, int n4) {
    int stride = gridDim.x * blockDim.x;
    for (int i = blockIdx.x * blockDim.x + threadIdx.x; i < n4; i += stride)
        out[i] = make_float4(0.f, 0.f, 0.f, 0.f);
}

// ---------------- edge kernel ----------------
// smem layout (floats):
//  W1s   [8][64]        @ 0       (512)
//  W2s   [64][128]      @ 512     (8192)
//  Wcs   [128][192]     @ 8704    (24576)   (Wtp0 | Wtp1) * 1/sqrt(128)
//  radS  [64][8]        @ 33280   (512)
//  h2f   [32][64][2]    @ 33792   (4096)    edge-pair packed h
//  nf2f  [32][128][2]   @ 37888   (8192)    edge-pair packed node_feats
//  y1S   [64][4]        @ 46080   (256)
//  sndS  [64] int, rcvS [64] int  @ 46336 floats
#define EDGE_SMEM_FLOATS 46336
#define EDGE_SMEM_BYTES (EDGE_SMEM_FLOATS * 4 + 64 * 4 * 2)

__global__ void __launch_bounds__(NTHREADS, 1)
edge_kernel(const float* __restrict__ node_attrs,
            const int* __restrict__ edge_index,
            const float* __restrict__ edge_vec,
            const float* __restrict__ edge_len,
            const float* __restrict__ W1,
            const float* __restrict__ W2,
            const float* __restrict__ Wtp0,
            const float* __restrict__ Wtp1,
            float* __restrict__ out) {
    extern __shared__ float smem[];
    float* W1s  = smem;
    float* W2s  = smem + 512;
    float* Wcs  = smem + 8704;
    float* radS = smem + 33280;
    float* h2f  = smem + 33792;
    float* nf2f = smem + 37888;
    float* y1S  = smem + 46080;
    int* sndS = (int*)(smem + EDGE_SMEM_FLOATS);
    int* rcvS = sndS + 64;

    const int tid = threadIdx.x;
    const int cg = tid & 31;       // column group (lane)
    const int eg = tid >> 5;       // edge group (warp)

    // stage weights once per block (persistent)
    const float s_w1 = 0.35355339059327373f;  // 1/sqrt(8)
    const float s_w2 = 0.125f;                // 1/sqrt(64)
    const float s_tp = 0.08838834764831845f;  // 1/sqrt(128)
    for (int i = tid; i < 8 * 64; i += NTHREADS)   W1s[i] = W1[i] * s_w1;
    for (int i = tid; i < 64 * 128; i += NTHREADS) W2s[i] = W2[i] * s_w2;
    for (int i = tid; i < 128 * 192; i += NTHREADS) {
        int k = i / 192, c = i % 192;
        float v = (c < 128) ? Wtp0[k * 128 + c] : Wtp1[k * 64 + (c - 128)];
        Wcs[i] = v * s_tp;
    }
    __syncthreads();

    const int ntiles = NE / TE;
    for (int tile = blockIdx.x; tile < ntiles; tile += gridDim.x) {
        const int ebase = tile * TE;

        // ---- Phase A: per-edge scalars ----
        if (tid < TE) {
            int e = ebase + tid;
            float x = edge_len[e];
            bool valid = (x > 0.f) && (x < 5.0f);
            float pref = valid ? (0.6324555320336759f / x) : 0.f;  // sqrt(2/5)/x
#pragma unroll
            for (int r = 0; r < 8; r++)
                radS[tid * 8 + r] = pref * sinf((float)(r + 1) * 0.6283185307179586f * x);
            float vx = edge_vec[e * 3 + 0];
            float vy = edge_vec[e * 3 + 1];
            float vz = edge_vec[e * 3 + 2];
            float rn = rsqrtf(vx * vx + vy * vy + vz * vz) * 1.7320508075688772f;
            y1S[tid * 4 + 0] = vy * rn;
            y1S[tid * 4 + 1] = vz * rn;
            y1S[tid * 4 + 2] = vx * rn;
            sndS[tid] = edge_index[e];
            rcvS[tid] = edge_index[NE + e];
        }
        __syncthreads();

        // ---- Phase B: h = SILU_2MOM * silu(rad @ W1') ----
        for (int idx = tid; idx < TE * 64; idx += NTHREADS) {
            int e = idx >> 6, j = idx & 63;
            float s = 0.f;
#pragma unroll
            for (int r = 0; r < 8; r++) s += radS[e * 8 + r] * W1s[r * 64 + j];
            float hv = 1.679177f * s / (1.f + expf(-s));
            h2f[((e >> 1) * 64 + j) * 2 + (e & 1)] = hv;
        }
        __syncthreads();

        // ---- Phase C: R_n = h @ W2', nf = node_attrs[snd] * R_n ----
        {
            u64 acc[4][4];
#pragma unroll
            for (int p = 0; p < 4; p++)
#pragma unroll
                for (int j = 0; j < 4; j++) acc[p][j] = 0ull;
#pragma unroll 4
            for (int j = 0; j < 64; j++) {
                u64 hv[4];
#pragma unroll
                for (int p = 0; p < 4; p++)
                    hv[p] = *(const u64*)&h2f[((eg * 4 + p) * 64 + j) * 2];
#pragma unroll
                for (int jj = 0; jj < 4; jj++) {
                    float w = W2s[j * 128 + cg + 32 * jj];
                    u64 wd = pack2(w, w);
#pragma unroll
                    for (int p = 0; p < 4; p++) fma2(acc[p][jj], hv[p], wd);
                }
            }
#pragma unroll
            for (int p = 0; p < 4; p++) {
                int pr = eg * 4 + p;
                int s0 = sndS[pr * 2], s1 = sndS[pr * 2 + 1];
#pragma unroll
                for (int jj = 0; jj < 4; jj++) {
                    int col = cg + 32 * jj;
                    float a, b;
                    unpack2(acc[p][jj], a, b);
                    a *= node_attrs[s0 * HID + col];
                    b *= node_attrs[s1 * HID + col];
                    *(float2*)&nf2f[(pr * HID + col) * 2] = make_float2(a, b);
                }
            }
        }
        __syncthreads();

        // ---- Phase D: [f0|t1] = nf @ Wcat ----
        u64 acc[4][6];
#pragma unroll
        for (int p = 0; p < 4; p++)
#pragma unroll
            for (int j = 0; j < 6; j++) acc[p][j] = 0ull;
#pragma unroll 2
        for (int k = 0; k < 128; k++) {
            u64 a[4];
#pragma unroll
            for (int p = 0; p < 4; p++)
                a[p] = *(const u64*)&nf2f[((eg * 4 + p) * HID + k) * 2];
#pragma unroll
            for (int j = 0; j < 6; j++) {
                float w = Wcs[k * 192 + cg + 32 * j];
                u64 wd = pack2(w, w);
#pragma unroll
                for (int p = 0; p < 4; p++) fma2(acc[p][j], a[p], wd);
            }
        }

        // ---- Phase E: scatter-add ----
#pragma unroll
        for (int p = 0; p < 4; p++) {
            int pr = eg * 4 + p;
            int el0 = pr * 2, el1 = el0 + 1;
            int r0 = rcvS[el0], r1 = rcvS[el1];
#pragma unroll
            for (int j = 0; j < 6; j++) {
                int col = cg + 32 * j;
                float a, b;
                unpack2(acc[p][j], a, b);
                if (col < 128) {
                    atomicAdd(&out[r0 * FEAT + col], a);
                    atomicAdd(&out[r1 * FEAT + col], b);
                } else {
                    int m = col - 128;
                    int b0 = r0 * FEAT + 128 + m * 3;
                    int b1 = r1 * FEAT + 128 + m * 3;
#pragma unroll
                    for (int c = 0; c < 3; c++) {
                        atomicAdd(&out[b0 + c], a * y1S[el0 * 4 + c]);
                        atomicAdd(&out[b1 + c], b * y1S[el1 * 4 + c]);
                    }
                }
            }
        }
        __syncthreads();  // protect shared reuse next tile
    }
}

// ---------------- node kernel ----------------
// smem: Wm [192][128] @0 (24576 floats), b2f [32][192][2] @24576 (12288 floats)
#define NODE_SMEM_FLOATS (24576 + 12288)
#define NODE_SMEM_BYTES (NODE_SMEM_FLOATS * 4)

__global__ void __launch_bounds__(NTHREADS, 1)
node_kernel(const float* __restrict__ Wmix0, float* __restrict__ out) {
    extern __shared__ float smem[];
    float* Wm  = smem;
    float* b2f = smem + 24576;
    const int tid = threadIdx.x;
    const int cg = tid & 31;
    const int eg = tid >> 5;

    const float s_mix = 0.07216878364870323f;  // 1/sqrt(192)
    for (int i = tid; i < 192 * 128; i += NTHREADS) Wm[i] = Wmix0[i] * s_mix;
    __syncthreads();

    const int ntiles = (NN + TE - 1) / TE;  // 782
    for (int tile = blockIdx.x; tile < ntiles; tile += gridDim.x) {
        // ---- Phase A: B0 tile ----
        for (int idx = tid; idx < TE * 192; idx += NTHREADS) {
            int e = idx / 192, k = idx % 192;
            int n = tile * TE + e;
            float v = 0.f;
            if (n < NN) {
                if (k < 128) {
                    float a = out[n * FEAT + k];
                    v = a * a;
                } else {
                    int m = k - 128;
                    const float* p = &out[n * FEAT + 128 + m * 3];
                    float a0 = p[0], a1 = p[1], a2 = p[2];
                    v = (a0 * a0 + a1 * a1 + a2 * a2) * 0.5773502691896258f;  // 1/sqrt(3)
                }
            }
            b2f[((e >> 1) * 192 + k) * 2 + (e & 1)] = v;
        }
        __syncthreads();

        // ---- Phase B: mix0 = B0 @ Wmix0' ----
        u64 acc[4][4];
#pragma unroll
        for (int p = 0; p < 4; p++)
#pragma unroll
            for (int j = 0; j < 4; j++) acc[p][j] = 0ull;
#pragma unroll 2
        for (int k = 0; k < 192; k++) {
            u64 a[4];
#pragma unroll
            for (int p = 0; p < 4; p++)
                a[p] = *(const u64*)&b2f[((eg * 4 + p) * 192 + k) * 2];
#pragma unroll
            for (int j = 0; j < 4; j++) {
                float w = Wm[k * 128 + cg + 32 * j];
                u64 wd = pack2(w, w);
#pragma unroll
                for (int p = 0; p < 4; p++) fma2(acc[p][j], a[p], wd);
            }
        }

        // ---- Phase C: out[:, :128] += mix0 ----
#pragma unroll
        for (int p = 0; p < 4; p++) {
            int n0 = tile * TE + (eg * 4 + p) * 2;
            int n1 = n0 + 1;
#pragma unroll
            for (int j = 0; j < 4; j++) {
                int col = cg + 32 * j;
                float a, b;
                unpack2(acc[p][j], a, b);
                if (n0 < NN) out[n0 * FEAT + col] += a;
                if (n1 < NN) out[n1 * FEAT + col] += b;
            }
        }
        __syncthreads();
    }
}

extern "C" void kernel_launch(void* const* d_in, const int* in_sizes, int n_in,
                              void* d_out, int out_size) {
    const float* node_attrs = (const float*)d_in[0];
    const int*   edge_index = (const int*)d_in[1];
    const float* edge_vec   = (const float*)d_in[2];
    const float* edge_len   = (const float*)d_in[3];
    const float* W1         = (const float*)d_in[4];
    const float* W2         = (const float*)d_in[5];
    const float* Wtp0       = (const float*)d_in[6];
    const float* Wtp1       = (const float*)d_in[7];
    const float* Wmix0      = (const float*)d_in[8];
    float* out = (float*)d_out;

    cudaFuncSetAttribute(edge_kernel, cudaFuncAttributeMaxDynamicSharedMemorySize, EDGE_SMEM_BYTES);
    cudaFuncSetAttribute(node_kernel, cudaFuncAttributeMaxDynamicSharedMemorySize, NODE_SMEM_BYTES);

    zero_kernel<<<4096, 256>>>((float4*)out, out_size / 4);
    edge_kernel<<<152, NTHREADS, EDGE_SMEM_BYTES>>>(
        node_attrs, edge_index, edge_vec, edge_len, W1, W2, Wtp0, Wtp1, out);
    node_kernel<<<152, NTHREADS, NODE_SMEM_BYTES>>>(Wmix0, out);
}

// round 2
// speedup vs baseline: 1.0347x; 1.0347x over previous
#include <cuda_runtime.h>
#include <math.h>

#define NN 50000
#define NE 400000
#define HID 128
#define MUL1 64
#define FEAT 320
#define TE 64
#define NTHREADS 512

typedef unsigned long long u64;

__device__ __forceinline__ u64 pack2(float a, float b) {
    u64 r; asm("mov.b64 %0, {%1,%2};" : "=l"(r) : "f"(a), "f"(b)); return r;
}
__device__ __forceinline__ void unpack2(u64 v, float& a, float& b) {
    asm("mov.b64 {%0,%1}, %2;" : "=f"(a), "=f"(b) : "l"(v));
}
__device__ __forceinline__ void fma2(u64& d, u64 a, u64 b) {
    asm("fma.rn.f32x2 %0, %1, %2, %0;" : "+l"(d) : "l"(a), "l"(b));
}
__device__ __forceinline__ void red4(float* p, float a, float b, float c, float d) {
    asm volatile("red.global.add.v4.f32 [%0], {%1,%2,%3,%4};"
                 :: "l"(p), "f"(a), "f"(b), "f"(c), "f"(d) : "memory");
}
__device__ __forceinline__ void red2(float* p, float a, float b) {
    asm volatile("red.global.add.v2.f32 [%0], {%1,%2};"
                 :: "l"(p), "f"(a), "f"(b) : "memory");
}

// ---------------- zero kernel ----------------
__global__ void zero_kernel(float4* out, int n4) {
    int stride = gridDim.x * blockDim.x;
    for (int i = blockIdx.x * blockDim.x + threadIdx.x; i < n4; i += stride)
        out[i] = make_float4(0.f, 0.f, 0.f, 0.f);
}

// ---------------- edge kernel ----------------
// smem layout (floats):
//  W1s   [8][64]        @ 0       (512)
//  W2s   [64][128]      @ 512     (8192)
//  Wcs   [128][192]     @ 8704    (24576)   (Wtp0 | Wtp1) * 1/sqrt(128)
//  radS  [64][8]        @ 33280   (512)
//  h2f   [32][64][2]    @ 33792   (4096)    edge-pair packed h
//  nf2f  [32][128][2]   @ 37888   (8192)    edge-pair packed node_feats
//  y1S   [64][4]        @ 46080   (256)
//  sndS  [64] int, rcvS [64] int  @ 46336 floats
#define EDGE_SMEM_FLOATS 46336
#define EDGE_SMEM_BYTES (EDGE_SMEM_FLOATS * 4 + 64 * 4 * 2)

__global__ void __launch_bounds__(NTHREADS, 1)
edge_kernel(const float* __restrict__ node_attrs,
            const int* __restrict__ edge_index,
            const float* __restrict__ edge_vec,
            const float* __restrict__ edge_len,
            const float* __restrict__ W1,
            const float* __restrict__ W2,
            const float* __restrict__ Wtp0,
            const float* __restrict__ Wtp1,
            float* __restrict__ out) {
    extern __shared__ float smem[];
    float* W1s  = smem;
    float* W2s  = smem + 512;
    float* Wcs  = smem + 8704;
    float* radS = smem + 33280;
    float* h2f  = smem + 33792;
    float* nf2f = smem + 37888;
    float* y1S  = smem + 46080;
    int* sndS = (int*)(smem + EDGE_SMEM_FLOATS);
    int* rcvS = sndS + 64;

    const int tid = threadIdx.x;
    const int cg = tid & 31;       // lane
    const int eg = tid >> 5;       // warp id (0..15), each warp owns 2 edge-pairs

    const float s_w1 = 0.35355339059327373f;  // 1/sqrt(8)
    const float s_w2 = 0.125f;                // 1/sqrt(64)
    const float s_tp = 0.08838834764831845f;  // 1/sqrt(128)
    for (int i = tid; i < 8 * 64; i += NTHREADS)   W1s[i] = W1[i] * s_w1;
    for (int i = tid; i < 64 * 128; i += NTHREADS) W2s[i] = W2[i] * s_w2;
    for (int i = tid; i < 128 * 192; i += NTHREADS) {
        int k = i / 192, c = i % 192;
        float v = (c < 128) ? Wtp0[k * 128 + c] : Wtp1[k * 64 + (c - 128)];
        Wcs[i] = v * s_tp;
    }
    __syncthreads();

    const int ntiles = NE / TE;
    for (int tile = blockIdx.x; tile < ntiles; tile += gridDim.x) {
        const int ebase = tile * TE;

        // ---- Phase A: per-edge scalars ----
        if (tid < TE) {
            int e = ebase + tid;
            float x = edge_len[e];
            bool valid = (x > 0.f) && (x < 5.0f);
            float pref = valid ? (0.6324555320336759f / x) : 0.f;  // sqrt(2/5)/x
#pragma unroll
            for (int r = 0; r < 8; r++)
                radS[tid * 8 + r] = pref * sinf((float)(r + 1) * 0.6283185307179586f * x);
            float vx = edge_vec[e * 3 + 0];
            float vy = edge_vec[e * 3 + 1];
            float vz = edge_vec[e * 3 + 2];
            float rn = rsqrtf(vx * vx + vy * vy + vz * vz) * 1.7320508075688772f;
            y1S[tid * 4 + 0] = vy * rn;
            y1S[tid * 4 + 1] = vz * rn;
            y1S[tid * 4 + 2] = vx * rn;
            sndS[tid] = edge_index[e];
            rcvS[tid] = edge_index[NE + e];
        }
        __syncthreads();

        // ---- Phase B: h = SILU_2MOM * silu(rad @ W1') ----
        for (int idx = tid; idx < TE * 64; idx += NTHREADS) {
            int e = idx >> 6, j = idx & 63;
            float s = 0.f;
#pragma unroll
            for (int r = 0; r < 8; r++) s += radS[e * 8 + r] * W1s[r * 64 + j];
            float hv = 1.679177f * s / (1.f + expf(-s));
            h2f[((e >> 1) * 64 + j) * 2 + (e & 1)] = hv;
        }
        __syncthreads();

        // ---- Phase C: R_n = h @ W2', nf = node_attrs[snd] * R_n ----
        {
            u64 acc[2][4];
#pragma unroll
            for (int p = 0; p < 2; p++)
#pragma unroll
                for (int j = 0; j < 4; j++) acc[p][j] = 0ull;
#pragma unroll 4
            for (int j = 0; j < 64; j++) {
                u64 hv[2];
#pragma unroll
                for (int p = 0; p < 2; p++)
                    hv[p] = *(const u64*)&h2f[((eg * 2 + p) * 64 + j) * 2];
#pragma unroll
                for (int jj = 0; jj < 4; jj++) {
                    float w = W2s[j * 128 + cg + 32 * jj];
                    u64 wd = pack2(w, w);
#pragma unroll
                    for (int p = 0; p < 2; p++) fma2(acc[p][jj], hv[p], wd);
                }
            }
#pragma unroll
            for (int p = 0; p < 2; p++) {
                int pr = eg * 2 + p;
                int s0 = sndS[pr * 2], s1 = sndS[pr * 2 + 1];
#pragma unroll
                for (int jj = 0; jj < 4; jj++) {
                    int col = cg + 32 * jj;
                    float a, b;
                    unpack2(acc[p][jj], a, b);
                    a *= node_attrs[s0 * HID + col];
                    b *= node_attrs[s1 * HID + col];
                    *(float2*)&nf2f[(pr * HID + col) * 2] = make_float2(a, b);
                }
            }
        }
        __syncthreads();

        // ---- Phase D: [f0|t1] = nf @ Wcat, contiguous-column ownership ----
        // thread owns f0 cols [4cg, 4cg+4) and t1 rows m in {2cg, 2cg+1}
        u64 acc0[2][4];  // f0
        u64 acc1[2][2];  // t1
#pragma unroll
        for (int p = 0; p < 2; p++) {
#pragma unroll
            for (int j = 0; j < 4; j++) acc0[p][j] = 0ull;
#pragma unroll
            for (int j = 0; j < 2; j++) acc1[p][j] = 0ull;
        }
#pragma unroll 2
        for (int k = 0; k < 128; k++) {
            u64 a[2];
#pragma unroll
            for (int p = 0; p < 2; p++)
                a[p] = *(const u64*)&nf2f[((eg * 2 + p) * HID + k) * 2];
            float4 w4 = *(const float4*)&Wcs[k * 192 + 4 * cg];
            float2 wt = *(const float2*)&Wcs[k * 192 + 128 + 2 * cg];
            u64 wd0 = pack2(w4.x, w4.x);
            u64 wd1 = pack2(w4.y, w4.y);
            u64 wd2 = pack2(w4.z, w4.z);
            u64 wd3 = pack2(w4.w, w4.w);
            u64 wt0 = pack2(wt.x, wt.x);
            u64 wt1 = pack2(wt.y, wt.y);
#pragma unroll
            for (int p = 0; p < 2; p++) {
                fma2(acc0[p][0], a[p], wd0);
                fma2(acc0[p][1], a[p], wd1);
                fma2(acc0[p][2], a[p], wd2);
                fma2(acc0[p][3], a[p], wd3);
                fma2(acc1[p][0], a[p], wt0);
                fma2(acc1[p][1], a[p], wt1);
            }
        }

        // ---- Phase E: vectorized scatter-add ----
#pragma unroll
        for (int p = 0; p < 2; p++) {
            int pr = eg * 2 + p;
            int el0 = pr * 2, el1 = el0 + 1;
            int r0 = rcvS[el0], r1 = rcvS[el1];

            // f0: one red.v4 per edge
            float a0, b0, a1, b1, a2, b2, a3, b3;
            unpack2(acc0[p][0], a0, b0);
            unpack2(acc0[p][1], a1, b1);
            unpack2(acc0[p][2], a2, b2);
            unpack2(acc0[p][3], a3, b3);
            red4(&out[(u64)r0 * FEAT + 4 * cg], a0, a1, a2, a3);
            red4(&out[(u64)r1 * FEAT + 4 * cg], b0, b1, b2, b3);

            // t1: 6 contiguous floats per edge (m = 2cg, 2cg+1)
            float u0a, u0b, u1a, u1b;
            unpack2(acc1[p][0], u0a, u0b);
            unpack2(acc1[p][1], u1a, u1b);
            float ya0 = y1S[el0 * 4 + 0], ya1 = y1S[el0 * 4 + 1], ya2 = y1S[el0 * 4 + 2];
            float yb0 = y1S[el1 * 4 + 0], yb1 = y1S[el1 * 4 + 1], yb2 = y1S[el1 * 4 + 2];
            float* p0 = &out[(u64)r0 * FEAT + 128 + 6 * cg];
            float* p1 = &out[(u64)r1 * FEAT + 128 + 6 * cg];
            float va[6] = {u0a * ya0, u0a * ya1, u0a * ya2, u1a * ya0, u1a * ya1, u1a * ya2};
            float vb[6] = {u0b * yb0, u0b * yb1, u0b * yb2, u1b * yb0, u1b * yb1, u1b * yb2};
            if ((cg & 1) == 0) {
                red4(p0, va[0], va[1], va[2], va[3]);
                red2(p0 + 4, va[4], va[5]);
                red4(p1, vb[0], vb[1], vb[2], vb[3]);
                red2(p1 + 4, vb[4], vb[5]);
            } else {
                red2(p0, va[0], va[1]);
                red4(p0 + 2, va[2], va[3], va[4], va[5]);
                red2(p1, vb[0], vb[1]);
                red4(p1 + 2, vb[2], vb[3], vb[4], vb[5]);
            }
        }
        __syncthreads();  // protect shared reuse next tile
    }
}

// ---------------- node kernel ----------------
// smem: Wm [192][128] @0 (24576 floats), b2f [32][192][2] @24576 (12288 floats)
#define NODE_SMEM_FLOATS (24576 + 12288)
#define NODE_SMEM_BYTES (NODE_SMEM_FLOATS * 4)

__global__ void __launch_bounds__(NTHREADS, 1)
node_kernel(const float* __restrict__ Wmix0, float* __restrict__ out) {
    extern __shared__ float smem[];
    float* Wm  = smem;
    float* b2f = smem + 24576;
    const int tid = threadIdx.x;
    const int cg = tid & 31;
    const int eg = tid >> 5;   // 16 warps, 2 node-pairs each

    const float s_mix = 0.07216878364870323f;  // 1/sqrt(192)
    for (int i = tid; i < 192 * 128; i += NTHREADS) Wm[i] = Wmix0[i] * s_mix;
    __syncthreads();

    const int ntiles = (NN + TE - 1) / TE;  // 782
    for (int tile = blockIdx.x; tile < ntiles; tile += gridDim.x) {
        // ---- Phase A: B0 tile ----
        for (int idx = tid; idx < TE * 192; idx += NTHREADS) {
            int e = idx / 192, k = idx % 192;
            int n = tile * TE + e;
            float v = 0.f;
            if (n < NN) {
                if (k < 128) {
                    float a = out[(u64)n * FEAT + k];
                    v = a * a;
                } else {
                    int m = k - 128;
                    const float* p = &out[(u64)n * FEAT + 128 + m * 3];
                    float a0 = p[0], a1 = p[1], a2 = p[2];
                    v = (a0 * a0 + a1 * a1 + a2 * a2) * 0.5773502691896258f;  // 1/sqrt(3)
                }
            }
            b2f[((e >> 1) * 192 + k) * 2 + (e & 1)] = v;
        }
        __syncthreads();

        // ---- Phase B: mix0 = B0 @ Wmix0', thread owns cols [4cg, 4cg+4) ----
        u64 acc[2][4];
#pragma unroll
        for (int p = 0; p < 2; p++)
#pragma unroll
            for (int j = 0; j < 4; j++) acc[p][j] = 0ull;
#pragma unroll 2
        for (int k = 0; k < 192; k++) {
            u64 a[2];
#pragma unroll
            for (int p = 0; p < 2; p++)
                a[p] = *(const u64*)&b2f[((eg * 2 + p) * 192 + k) * 2];
            float4 w4 = *(const float4*)&Wm[k * 128 + 4 * cg];
            u64 wd0 = pack2(w4.x, w4.x);
            u64 wd1 = pack2(w4.y, w4.y);
            u64 wd2 = pack2(w4.z, w4.z);
            u64 wd3 = pack2(w4.w, w4.w);
#pragma unroll
            for (int p = 0; p < 2; p++) {
                fma2(acc[p][0], a[p], wd0);
                fma2(acc[p][1], a[p], wd1);
                fma2(acc[p][2], a[p], wd2);
                fma2(acc[p][3], a[p], wd3);
            }
        }

        // ---- Phase C: out[:, :128] += mix0, float4 RMW ----
#pragma unroll
        for (int p = 0; p < 2; p++) {
            int n0 = tile * TE + (eg * 2 + p) * 2;
            int n1 = n0 + 1;
            float a0, b0, a1, b1, a2, b2, a3, b3;
            unpack2(acc[p][0], a0, b0);
            unpack2(acc[p][1], a1, b1);
            unpack2(acc[p][2], a2, b2);
            unpack2(acc[p][3], a3, b3);
            if (n0 < NN) {
                float4* q = (float4*)&out[(u64)n0 * FEAT + 4 * cg];
                float4 v = *q;
                v.x += a0; v.y += a1; v.z += a2; v.w += a3;
                *q = v;
            }
            if (n1 < NN) {
                float4* q = (float4*)&out[(u64)n1 * FEAT + 4 * cg];
                float4 v = *q;
                v.x += b0; v.y += b1; v.z += b2; v.w += b3;
                *q = v;
            }
        }
        __syncthreads();
    }
}

extern "C" void kernel_launch(void* const* d_in, const int* in_sizes, int n_in,
                              void* d_out, int out_size) {
    const float* node_attrs = (const float*)d_in[0];
    const int*   edge_index = (const int*)d_in[1];
    const float* edge_vec   = (const float*)d_in[2];
    const float* edge_len   = (const float*)d_in[3];
    const float* W1         = (const float*)d_in[4];
    const float* W2         = (const float*)d_in[5];
    const float* Wtp0       = (const float*)d_in[6];
    const float* Wtp1       = (const float*)d_in[7];
    const float* Wmix0      = (const float*)d_in[8];
    float* out = (float*)d_out;

    cudaFuncSetAttribute(edge_kernel, cudaFuncAttributeMaxDynamicSharedMemorySize, EDGE_SMEM_BYTES);
    cudaFuncSetAttribute(node_kernel, cudaFuncAttributeMaxDynamicSharedMemorySize, NODE_SMEM_BYTES);

    zero_kernel<<<4096, 256>>>((float4*)out, out_size / 4);
    edge_kernel<<<152, NTHREADS, EDGE_SMEM_BYTES>>>(
        node_attrs, edge_index, edge_vec, edge_len, W1, W2, Wtp0, Wtp1, out);
    node_kernel<<<152, NTHREADS, NODE_SMEM_BYTES>>>(Wmix0, out);
}

// round 3
// speedup vs baseline: 1.0438x; 1.0088x over previous
#include <cuda_runtime.h>
#include <math.h>

#define NN 50000
#define NE 400000
#define HID 128
#define MUL1 64
#define FEAT 320
#define TE 64
#define NTHREADS 512

typedef unsigned long long u64;

__device__ __forceinline__ u64 pack2(float a, float b) {
    u64 r; asm("mov.b64 %0, {%1,%2};" : "=l"(r) : "f"(a), "f"(b)); return r;
}
__device__ __forceinline__ void unpack2(u64 v, float& a, float& b) {
    asm("mov.b64 {%0,%1}, %2;" : "=f"(a), "=f"(b) : "l"(v));
}
__device__ __forceinline__ void fma2(u64& d, u64 a, u64 b) {
    asm("fma.rn.f32x2 %0, %1, %2, %0;" : "+l"(d) : "l"(a), "l"(b));
}
__device__ __forceinline__ void red4(float* p, float a, float b, float c, float d) {
    asm volatile("red.global.add.v4.f32 [%0], {%1,%2,%3,%4};"
                 :: "l"(p), "f"(a), "f"(b), "f"(c), "f"(d) : "memory");
}
__device__ __forceinline__ void red2(float* p, float a, float b) {
    asm volatile("red.global.add.v2.f32 [%0], {%1,%2};"
                 :: "l"(p), "f"(a), "f"(b) : "memory");
}

// ---------------- zero kernel ----------------
__global__ void zero_kernel(float4* out, int n4) {
    int stride = gridDim.x * blockDim.x;
    for (int i = blockIdx.x * blockDim.x + threadIdx.x; i < n4; i += stride)
        out[i] = make_float4(0.f, 0.f, 0.f, 0.f);
}

// ---------------- edge kernel ----------------
// smem layout (floats):
//  W1s   [8][64]        @ 0       (512)
//  W2s   [64][128]      @ 512     (8192)
//  Wcs   [128][192]     @ 8704    (24576)   (Wtp0 | Wtp1) * 1/sqrt(128)
//  radS  [64][8]        @ 33280   (512)
//  h2f   [32][64][2]    @ 33792   (4096)    edge-pair packed h
//  nf2f  [32][128][2]   @ 37888   (8192)    edge-pair packed node_feats
//  y1S   [64][4]        @ 46080   (256)
//  sndS  [64] int, rcvS [64] int  @ 46336 floats
#define EDGE_SMEM_FLOATS 46336
#define EDGE_SMEM_BYTES (EDGE_SMEM_FLOATS * 4 + 64 * 4 * 2)

__global__ void __launch_bounds__(NTHREADS, 1)
edge_kernel(const float* __restrict__ node_attrs,
            const int* __restrict__ edge_index,
            const float* __restrict__ edge_vec,
            const float* __restrict__ edge_len,
            const float* __restrict__ W1,
            const float* __restrict__ W2,
            const float* __restrict__ Wtp0,
            const float* __restrict__ Wtp1,
            float* __restrict__ out) {
    extern __shared__ float smem[];
    float* W1s  = smem;
    float* W2s  = smem + 512;
    float* Wcs  = smem + 8704;
    float* radS = smem + 33280;
    float* h2f  = smem + 33792;
    float* nf2f = smem + 37888;
    float* y1S  = smem + 46080;
    int* sndS = (int*)(smem + EDGE_SMEM_FLOATS);
    int* rcvS = sndS + 64;

    const int tid = threadIdx.x;
    const int cg = tid & 31;       // lane
    const int eg = tid >> 5;       // warp id (0..15), each warp owns 2 edge-pairs

    const float s_w1 = 0.35355339059327373f;  // 1/sqrt(8)
    const float s_w2 = 0.125f;                // 1/sqrt(64)
    const float s_tp = 0.08838834764831845f;  // 1/sqrt(128)
    for (int i = tid; i < 8 * 64; i += NTHREADS)   W1s[i] = W1[i] * s_w1;
    for (int i = tid; i < 64 * 128; i += NTHREADS) W2s[i] = W2[i] * s_w2;
    for (int i = tid; i < 128 * 192; i += NTHREADS) {
        int k = i / 192, c = i % 192;
        float v = (c < 128) ? Wtp0[k * 128 + c] : Wtp1[k * 64 + (c - 128)];
        Wcs[i] = v * s_tp;
    }
    __syncthreads();

    const int ntiles = NE / TE;
    for (int tile = blockIdx.x; tile < ntiles; tile += gridDim.x) {
        const int ebase = tile * TE;

        // ---- Phase A: per-edge scalars ----
        if (tid < TE) {
            int e = ebase + tid;
            float x = edge_len[e];
            bool valid = (x > 0.f) && (x < 5.0f);
            float pref = valid ? (0.6324555320336759f / x) : 0.f;  // sqrt(2/5)/x
#pragma unroll
            for (int r = 0; r < 8; r++)
                radS[tid * 8 + r] = pref * sinf((float)(r + 1) * 0.6283185307179586f * x);
            float vx = edge_vec[e * 3 + 0];
            float vy = edge_vec[e * 3 + 1];
            float vz = edge_vec[e * 3 + 2];
            float rn = rsqrtf(vx * vx + vy * vy + vz * vz) * 1.7320508075688772f;
            y1S[tid * 4 + 0] = vy * rn;
            y1S[tid * 4 + 1] = vz * rn;
            y1S[tid * 4 + 2] = vx * rn;
            sndS[tid] = edge_index[e];
            rcvS[tid] = edge_index[NE + e];
        }
        __syncthreads();

        // ---- Phase B: h = SILU_2MOM * silu(rad @ W1') ----
        for (int idx = tid; idx < TE * 64; idx += NTHREADS) {
            int e = idx >> 6, j = idx & 63;
            float s = 0.f;
#pragma unroll
            for (int r = 0; r < 8; r++) s += radS[e * 8 + r] * W1s[r * 64 + j];
            float hv = 1.679177f * s / (1.f + expf(-s));
            h2f[((e >> 1) * 64 + j) * 2 + (e & 1)] = hv;
        }
        __syncthreads();

        // ---- Phase C: R_n = h @ W2', nf = node_attrs[snd] * R_n ----
        {
            u64 acc[2][4];
#pragma unroll
            for (int p = 0; p < 2; p++)
#pragma unroll
                for (int j = 0; j < 4; j++) acc[p][j] = 0ull;
#pragma unroll 4
            for (int j = 0; j < 64; j++) {
                u64 hv[2];
#pragma unroll
                for (int p = 0; p < 2; p++)
                    hv[p] = *(const u64*)&h2f[((eg * 2 + p) * 64 + j) * 2];
#pragma unroll
                for (int jj = 0; jj < 4; jj++) {
                    float w = W2s[j * 128 + cg + 32 * jj];
                    u64 wd = pack2(w, w);
#pragma unroll
                    for (int p = 0; p < 2; p++) fma2(acc[p][jj], hv[p], wd);
                }
            }
#pragma unroll
            for (int p = 0; p < 2; p++) {
                int pr = eg * 2 + p;
                int s0 = sndS[pr * 2], s1 = sndS[pr * 2 + 1];
#pragma unroll
                for (int jj = 0; jj < 4; jj++) {
                    int col = cg + 32 * jj;
                    float a, b;
                    unpack2(acc[p][jj], a, b);
                    a *= node_attrs[s0 * HID + col];
                    b *= node_attrs[s1 * HID + col];
                    *(float2*)&nf2f[(pr * HID + col) * 2] = make_float2(a, b);
                }
            }
        }
        __syncthreads();

        // ---- Phase D: [f0|t1] = nf @ Wcat, contiguous-column ownership ----
        // thread owns f0 cols [4cg, 4cg+4) and t1 rows m in {2cg, 2cg+1}
        u64 acc0[2][4];  // f0
        u64 acc1[2][2];  // t1
#pragma unroll
        for (int p = 0; p < 2; p++) {
#pragma unroll
            for (int j = 0; j < 4; j++) acc0[p][j] = 0ull;
#pragma unroll
            for (int j = 0; j < 2; j++) acc1[p][j] = 0ull;
        }
#pragma unroll 2
        for (int k = 0; k < 128; k++) {
            u64 a[2];
#pragma unroll
            for (int p = 0; p < 2; p++)
                a[p] = *(const u64*)&nf2f[((eg * 2 + p) * HID + k) * 2];
            float4 w4 = *(const float4*)&Wcs[k * 192 + 4 * cg];
            float2 wt = *(const float2*)&Wcs[k * 192 + 128 + 2 * cg];
            u64 wd0 = pack2(w4.x, w4.x);
            u64 wd1 = pack2(w4.y, w4.y);
            u64 wd2 = pack2(w4.z, w4.z);
            u64 wd3 = pack2(w4.w, w4.w);
            u64 wt0 = pack2(wt.x, wt.x);
            u64 wt1 = pack2(wt.y, wt.y);
#pragma unroll
            for (int p = 0; p < 2; p++) {
                fma2(acc0[p][0], a[p], wd0);
                fma2(acc0[p][1], a[p], wd1);
                fma2(acc0[p][2], a[p], wd2);
                fma2(acc0[p][3], a[p], wd3);
                fma2(acc1[p][0], a[p], wt0);
                fma2(acc1[p][1], a[p], wt1);
            }
        }

        // ---- Phase E: vectorized scatter-add ----
#pragma unroll
        for (int p = 0; p < 2; p++) {
            int pr = eg * 2 + p;
            int el0 = pr * 2, el1 = el0 + 1;
            int r0 = rcvS[el0], r1 = rcvS[el1];

            // f0: one red.v4 per edge
            float a0, b0, a1, b1, a2, b2, a3, b3;
            unpack2(acc0[p][0], a0, b0);
            unpack2(acc0[p][1], a1, b1);
            unpack2(acc0[p][2], a2, b2);
            unpack2(acc0[p][3], a3, b3);
            red4(&out[(u64)r0 * FEAT + 4 * cg], a0, a1, a2, a3);
            red4(&out[(u64)r1 * FEAT + 4 * cg], b0, b1, b2, b3);

            // t1: 6 contiguous floats per edge (m = 2cg, 2cg+1)
            float u0a, u0b, u1a, u1b;
            unpack2(acc1[p][0], u0a, u0b);
            unpack2(acc1[p][1], u1a, u1b);
            float ya0 = y1S[el0 * 4 + 0], ya1 = y1S[el0 * 4 + 1], ya2 = y1S[el0 * 4 + 2];
            float yb0 = y1S[el1 * 4 + 0], yb1 = y1S[el1 * 4 + 1], yb2 = y1S[el1 * 4 + 2];
            float* p0 = &out[(u64)r0 * FEAT + 128 + 6 * cg];
            float* p1 = &out[(u64)r1 * FEAT + 128 + 6 * cg];
            float va[6] = {u0a * ya0, u0a * ya1, u0a * ya2, u1a * ya0, u1a * ya1, u1a * ya2};
            float vb[6] = {u0b * yb0, u0b * yb1, u0b * yb2, u1b * yb0, u1b * yb1, u1b * yb2};
            if ((cg & 1) == 0) {
                red4(p0, va[0], va[1], va[2], va[3]);
                red2(p0 + 4, va[4], va[5]);
                red4(p1, vb[0], vb[1], vb[2], vb[3]);
                red2(p1 + 4, vb[4], vb[5]);
            } else {
                red2(p0, va[0], va[1]);
                red4(p0 + 2, va[2], va[3], va[4], va[5]);
                red2(p1, vb[0], vb[1]);
                red4(p1 + 2, vb[2], vb[3], vb[4], vb[5]);
            }
        }
        __syncthreads();  // protect shared reuse next tile
    }
}

// ---------------- node kernel ----------------
// smem: Wm [192][128] @0 (24576 floats), b2f [32][192][2] @24576 (12288 floats)
#define NODE_SMEM_FLOATS (24576 + 12288)
#define NODE_SMEM_BYTES (NODE_SMEM_FLOATS * 4)

__global__ void __launch_bounds__(NTHREADS, 1)
node_kernel(const float* __restrict__ Wmix0, float* __restrict__ out) {
    extern __shared__ float smem[];
    float* Wm  = smem;
    float* b2f = smem + 24576;
    const int tid = threadIdx.x;
    const int cg = tid & 31;
    const int eg = tid >> 5;   // 16 warps, 2 node-pairs each

    const float s_mix = 0.07216878364870323f;  // 1/sqrt(192)
    for (int i = tid; i < 192 * 128; i += NTHREADS) Wm[i] = Wmix0[i] * s_mix;
    __syncthreads();

    const int ntiles = (NN + TE - 1) / TE;  // 782
    for (int tile = blockIdx.x; tile < ntiles; tile += gridDim.x) {
        // ---- Phase A: B0 tile ----
        for (int idx = tid; idx < TE * 192; idx += NTHREADS) {
            int e = idx / 192, k = idx % 192;
            int n = tile * TE + e;
            float v = 0.f;
            if (n < NN) {
                if (k < 128) {
                    float a = out[(u64)n * FEAT + k];
                    v = a * a;
                } else {
                    int m = k - 128;
                    const float* p = &out[(u64)n * FEAT + 128 + m * 3];
                    float a0 = p[0], a1 = p[1], a2 = p[2];
                    v = (a0 * a0 + a1 * a1 + a2 * a2) * 0.5773502691896258f;  // 1/sqrt(3)
                }
            }
            b2f[((e >> 1) * 192 + k) * 2 + (e & 1)] = v;
        }
        __syncthreads();

        // ---- Phase B: mix0 = B0 @ Wmix0', thread owns cols [4cg, 4cg+4) ----
        u64 acc[2][4];
#pragma unroll
        for (int p = 0; p < 2; p++)
#pragma unroll
            for (int j = 0; j < 4; j++) acc[p][j] = 0ull;
#pragma unroll 2
        for (int k = 0; k < 192; k++) {
            u64 a[2];
#pragma unroll
            for (int p = 0; p < 2; p++)
                a[p] = *(const u64*)&b2f[((eg * 2 + p) * 192 + k) * 2];
            float4 w4 = *(const float4*)&Wm[k * 128 + 4 * cg];
            u64 wd0 = pack2(w4.x, w4.x);
            u64 wd1 = pack2(w4.y, w4.y);
            u64 wd2 = pack2(w4.z, w4.z);
            u64 wd3 = pack2(w4.w, w4.w);
#pragma unroll
            for (int p = 0; p < 2; p++) {
                fma2(acc[p][0], a[p], wd0);
                fma2(acc[p][1], a[p], wd1);
                fma2(acc[p][2], a[p], wd2);
                fma2(acc[p][3], a[p], wd3);
            }
        }

        // ---- Phase C: out[:, :128] += mix0, float4 RMW ----
#pragma unroll
        for (int p = 0; p < 2; p++) {
            int n0 = tile * TE + (eg * 2 + p) * 2;
            int n1 = n0 + 1;
            float a0, b0, a1, b1, a2, b2, a3, b3;
            unpack2(acc[p][0], a0, b0);
            unpack2(acc[p][1], a1, b1);
            unpack2(acc[p][2], a2, b2);
            unpack2(acc[p][3], a3, b3);
            if (n0 < NN) {
                float4* q = (float4*)&out[(u64)n0 * FEAT + 4 * cg];
                float4 v = *q;
                v.x += a0; v.y += a1; v.z += a2; v.w += a3;
                *q = v;
            }
            if (n1 < NN) {
                float4* q = (float4*)&out[(u64)n1 * FEAT + 4 * cg];
                float4 v = *q;
                v.x += b0; v.y += b1; v.z += b2; v.w += b3;
                *q = v;
            }
        }
        __syncthreads();
    }
}

extern "C" void kernel_launch(void* const* d_in, const int* in_sizes, int n_in,
                              void* d_out, int out_size) {
    const float* node_attrs = (const float*)d_in[0];
    const int*   edge_index = (const int*)d_in[1];
    const float* edge_vec   = (const float*)d_in[2];
    const float* edge_len   = (const float*)d_in[3];
    const float* W1         = (const float*)d_in[4];
    const float* W2         = (const float*)d_in[5];
    const float* Wtp0       = (const float*)d_in[6];
    const float* Wtp1       = (const float*)d_in[7];
    const float* Wmix0      = (const float*)d_in[8];
    float* out = (float*)d_out;

    cudaFuncSetAttribute(edge_kernel, cudaFuncAttributeMaxDynamicSharedMemorySize, EDGE_SMEM_BYTES);
    cudaFuncSetAttribute(node_kernel, cudaFuncAttributeMaxDynamicSharedMemorySize, NODE_SMEM_BYTES);

    zero_kernel<<<4096, 256>>>((float4*)out, out_size / 4);
    edge_kernel<<<152, NTHREADS, EDGE_SMEM_BYTES>>>(
        node_attrs, edge_index, edge_vec, edge_len, W1, W2, Wtp0, Wtp1, out);
    node_kernel<<<152, NTHREADS, NODE_SMEM_BYTES>>>(Wmix0, out);
}

// round 4
// speedup vs baseline: 1.1193x; 1.0723x over previous
#include <cuda_runtime.h>
#include <math.h>

#define NN 50000
#define NE 400000
#define HID 128
#define MUL1 64
#define FEAT 320
#define TE 96          // edges per tile (48 pairs, 16 warps x 3 pairs)
#define TN 64          // nodes per tile in node phase
#define NTHREADS 512
#define NBLOCKS 148

typedef unsigned long long u64;

__device__ __forceinline__ u64 pack2(float a, float b) {
    u64 r; asm("mov.b64 %0, {%1,%2};" : "=l"(r) : "f"(a), "f"(b)); return r;
}
__device__ __forceinline__ void unpack2(u64 v, float& a, float& b) {
    asm("mov.b64 {%0,%1}, %2;" : "=f"(a), "=f"(b) : "l"(v));
}
__device__ __forceinline__ void fma2(u64& d, u64 a, u64 b) {
    asm("fma.rn.f32x2 %0, %1, %2, %0;" : "+l"(d) : "l"(a), "l"(b));
}
__device__ __forceinline__ void red4(float* p, float a, float b, float c, float d) {
    asm volatile("red.global.add.v4.f32 [%0], {%1,%2,%3,%4};"
                 :: "l"(p), "f"(a), "f"(b), "f"(c), "f"(d) : "memory");
}
__device__ __forceinline__ void red2(float* p, float a, float b) {
    asm volatile("red.global.add.v2.f32 [%0], {%1,%2};"
                 :: "l"(p), "f"(a), "f"(b) : "memory");
}

// 64 MB scratch accumulator. Zero-initialized at module load; the node phase
// re-zeroes every element it consumes, restoring the invariant for the next
// replay (deterministic: identical work every call).
__device__ float g_A[(size_t)NN * FEAT];
__device__ unsigned int g_arrive;
__device__ unsigned int g_depart;

// smem float offsets (edge phase)
#define OW1   0        // [8][64]         512
#define OW2   512      // [64][128]       8192
#define OWC   8704     // [128][192]      24576
#define ORAD  33280    // [96][8]         768
#define OH2   34048    // [48][64][2]     6144
#define ONF   40192    // [48][128][2]    12288
#define OY1   52480    // [96][4]         384
#define OIDX  52864    // snd[96], rcv[96] ints
#define SMEM_FLOATS 53056
#define SMEM_BYTES (SMEM_FLOATS * 4)
// node phase overlay: Wm [192][128] @0 (24576), b2f [32][192][2] @24576 (12288)

__global__ void __launch_bounds__(NTHREADS, 1)
ace_fused_kernel(const float* __restrict__ node_attrs,
                 const int* __restrict__ edge_index,
                 const float* __restrict__ edge_vec,
                 const float* __restrict__ edge_len,
                 const float* __restrict__ W1,
                 const float* __restrict__ W2,
                 const float* __restrict__ Wtp0,
                 const float* __restrict__ Wtp1,
                 const float* __restrict__ Wmix0,
                 float* __restrict__ out) {
    extern __shared__ float smem[];
    float* W1s  = smem + OW1;
    float* W2s  = smem + OW2;
    float* Wcs  = smem + OWC;
    float* radS = smem + ORAD;
    float* h2f  = smem + OH2;
    float* nf2f = smem + ONF;
    float* y1S  = smem + OY1;
    int* sndS = (int*)(smem + OIDX);
    int* rcvS = sndS + TE;

    const int tid = threadIdx.x;
    const int cg = tid & 31;       // lane
    const int eg = tid >> 5;       // warp id (0..15), 3 edge-pairs each

    // ---------------- stage edge weights ----------------
    const float s_w1 = 0.35355339059327373f;  // 1/sqrt(8)
    const float s_w2 = 0.125f;                // 1/sqrt(64)
    const float s_tp = 0.08838834764831845f;  // 1/sqrt(128)
    for (int i = tid; i < 8 * 64; i += NTHREADS)   W1s[i] = W1[i] * s_w1;
    for (int i = tid; i < 64 * 128; i += NTHREADS) W2s[i] = W2[i] * s_w2;
    for (int i = tid; i < 128 * 192; i += NTHREADS) {
        int k = i / 192, c = i % 192;
        float v = (c < 128) ? Wtp0[k * 128 + c] : Wtp1[k * 64 + (c - 128)];
        Wcs[i] = v * s_tp;
    }
    __syncthreads();

    // ================= EDGE PHASE =================
    const int ntiles = (NE + TE - 1) / TE;  // 4167
    for (int tile = blockIdx.x; tile < ntiles; tile += gridDim.x) {
        const int ebase = tile * TE;

        // ---- Phase A: per-edge scalars ----
        if (tid < TE) {
            int e = ebase + tid;
            bool inrange = (e < NE);
            float x = inrange ? edge_len[e] : 1.0f;
            bool valid = inrange && (x > 0.f) && (x < 5.0f);
            float pref = valid ? (0.6324555320336759f / x) : 0.f;  // sqrt(2/5)/x
#pragma unroll
            for (int r = 0; r < 8; r++)
                radS[tid * 8 + r] = pref * sinf((float)(r + 1) * 0.6283185307179586f * x);
            float vx = 0.f, vy = 0.f, vz = 1.f;
            if (inrange) {
                vx = edge_vec[e * 3 + 0];
                vy = edge_vec[e * 3 + 1];
                vz = edge_vec[e * 3 + 2];
            }
            float rn = rsqrtf(vx * vx + vy * vy + vz * vz) * 1.7320508075688772f;
            y1S[tid * 4 + 0] = vy * rn;
            y1S[tid * 4 + 1] = vz * rn;
            y1S[tid * 4 + 2] = vx * rn;
            sndS[tid] = inrange ? edge_index[e] : 0;
            rcvS[tid] = inrange ? edge_index[NE + e] : 0;
        }
        __syncthreads();

        // ---- Phase B: h = SILU_2MOM * silu(rad @ W1') ----
        for (int idx = tid; idx < TE * 64; idx += NTHREADS) {
            int e = idx >> 6, j = idx & 63;
            float s = 0.f;
#pragma unroll
            for (int r = 0; r < 8; r++) s += radS[e * 8 + r] * W1s[r * 64 + j];
            float hv = 1.679177f * s / (1.f + expf(-s));
            h2f[((e >> 1) * 64 + j) * 2 + (e & 1)] = hv;
        }
        __syncthreads();

        // ---- Phase C: R_n = h @ W2', nf = node_attrs[snd] * R_n ----
        {
            u64 acc[3][4];
#pragma unroll
            for (int p = 0; p < 3; p++)
#pragma unroll
                for (int c = 0; c < 4; c++) acc[p][c] = 0ull;
#pragma unroll 4
            for (int j = 0; j < 64; j++) {
                u64 hv[3];
#pragma unroll
                for (int p = 0; p < 3; p++)
                    hv[p] = *(const u64*)&h2f[((eg * 3 + p) * 64 + j) * 2];
                float4 w4 = *(const float4*)&W2s[j * 128 + 4 * cg];
                u64 wd0 = pack2(w4.x, w4.x);
                u64 wd1 = pack2(w4.y, w4.y);
                u64 wd2 = pack2(w4.z, w4.z);
                u64 wd3 = pack2(w4.w, w4.w);
#pragma unroll
                for (int p = 0; p < 3; p++) {
                    fma2(acc[p][0], hv[p], wd0);
                    fma2(acc[p][1], hv[p], wd1);
                    fma2(acc[p][2], hv[p], wd2);
                    fma2(acc[p][3], hv[p], wd3);
                }
            }
#pragma unroll
            for (int p = 0; p < 3; p++) {
                int pr = eg * 3 + p;
                int s0 = sndS[pr * 2], s1 = sndS[pr * 2 + 1];
                float4 at0 = *(const float4*)&node_attrs[(u64)s0 * HID + 4 * cg];
                float4 at1 = *(const float4*)&node_attrs[(u64)s1 * HID + 4 * cg];
                float a0, b0, a1, b1, a2, b2, a3, b3;
                unpack2(acc[p][0], a0, b0);
                unpack2(acc[p][1], a1, b1);
                unpack2(acc[p][2], a2, b2);
                unpack2(acc[p][3], a3, b3);
                a0 *= at0.x; a1 *= at0.y; a2 *= at0.z; a3 *= at0.w;
                b0 *= at1.x; b1 *= at1.y; b2 *= at1.z; b3 *= at1.w;
                float* base = &nf2f[(pr * HID + 4 * cg) * 2];
                *(float4*)base       = make_float4(a0, b0, a1, b1);
                *(float4*)(base + 4) = make_float4(a2, b2, a3, b3);
            }
        }
        __syncthreads();

        // ---- Phase D: [f0|t1] = nf @ Wcat ----
        u64 acc0[3][4];  // f0 cols 4cg..4cg+3
        u64 acc1[3][2];  // t1 rows 2cg, 2cg+1
#pragma unroll
        for (int p = 0; p < 3; p++) {
#pragma unroll
            for (int c = 0; c < 4; c++) acc0[p][c] = 0ull;
            acc1[p][0] = 0ull; acc1[p][1] = 0ull;
        }
#pragma unroll 2
        for (int k = 0; k < 128; k++) {
            u64 a[3];
#pragma unroll
            for (int p = 0; p < 3; p++)
                a[p] = *(const u64*)&nf2f[((eg * 3 + p) * HID + k) * 2];
            float4 w4 = *(const float4*)&Wcs[k * 192 + 4 * cg];
            float2 wt = *(const float2*)&Wcs[k * 192 + 128 + 2 * cg];
            u64 wd0 = pack2(w4.x, w4.x);
            u64 wd1 = pack2(w4.y, w4.y);
            u64 wd2 = pack2(w4.z, w4.z);
            u64 wd3 = pack2(w4.w, w4.w);
            u64 wt0 = pack2(wt.x, wt.x);
            u64 wt1 = pack2(wt.y, wt.y);
#pragma unroll
            for (int p = 0; p < 3; p++) {
                fma2(acc0[p][0], a[p], wd0);
                fma2(acc0[p][1], a[p], wd1);
                fma2(acc0[p][2], a[p], wd2);
                fma2(acc0[p][3], a[p], wd3);
                fma2(acc1[p][0], a[p], wt0);
                fma2(acc1[p][1], a[p], wt1);
            }
        }

        // ---- Phase E: vectorized scatter-add into g_A ----
#pragma unroll
        for (int p = 0; p < 3; p++) {
            int pr = eg * 3 + p;
            int el0 = pr * 2, el1 = el0 + 1;
            int r0 = rcvS[el0], r1 = rcvS[el1];

            float a0, b0, a1, b1, a2, b2, a3, b3;
            unpack2(acc0[p][0], a0, b0);
            unpack2(acc0[p][1], a1, b1);
            unpack2(acc0[p][2], a2, b2);
            unpack2(acc0[p][3], a3, b3);
            red4(&g_A[(u64)r0 * FEAT + 4 * cg], a0, a1, a2, a3);
            red4(&g_A[(u64)r1 * FEAT + 4 * cg], b0, b1, b2, b3);

            float u0a, u0b, u1a, u1b;
            unpack2(acc1[p][0], u0a, u0b);
            unpack2(acc1[p][1], u1a, u1b);
            float ya0 = y1S[el0 * 4 + 0], ya1 = y1S[el0 * 4 + 1], ya2 = y1S[el0 * 4 + 2];
            float yb0 = y1S[el1 * 4 + 0], yb1 = y1S[el1 * 4 + 1], yb2 = y1S[el1 * 4 + 2];
            float* p0 = &g_A[(u64)r0 * FEAT + 128 + 6 * cg];
            float* p1 = &g_A[(u64)r1 * FEAT + 128 + 6 * cg];
            float va[6] = {u0a * ya0, u0a * ya1, u0a * ya2, u1a * ya0, u1a * ya1, u1a * ya2};
            float vb[6] = {u0b * yb0, u0b * yb1, u0b * yb2, u1b * yb0, u1b * yb1, u1b * yb2};
            if ((cg & 1) == 0) {
                red4(p0, va[0], va[1], va[2], va[3]);
                red2(p0 + 4, va[4], va[5]);
                red4(p1, vb[0], vb[1], vb[2], vb[3]);
                red2(p1 + 4, vb[4], vb[5]);
            } else {
                red2(p0, va[0], va[1]);
                red4(p0 + 2, va[2], va[3], va[4], va[5]);
                red2(p1, vb[0], vb[1]);
                red4(p1 + 2, vb[2], vb[3], vb[4], vb[5]);
            }
        }
        __syncthreads();  // protect shared reuse next tile
    }

    // ================= GRID BARRIER =================
    __threadfence();
    __syncthreads();
    if (tid == 0) {
        atomicAdd(&g_arrive, 1u);
        while (*(volatile unsigned int*)&g_arrive < (unsigned)gridDim.x)
            __nanosleep(128);
    }
    __syncthreads();
    __threadfence();

    // ================= NODE PHASE =================
    float* Wm  = smem;          // overlay (weights region dead now)
    float* b2f = smem + 24576;

    const float s_mix = 0.07216878364870323f;  // 1/sqrt(192)
    for (int i = tid; i < 192 * 128; i += NTHREADS) Wm[i] = Wmix0[i] * s_mix;
    __syncthreads();

    const int ntilesN = (NN + TN - 1) / TN;  // 782
    for (int tile = blockIdx.x; tile < ntilesN; tile += gridDim.x) {
        const int nbase = tile * TN;

        // ---- build B0 tile (reads g_A) ----
        for (int idx = tid; idx < TN * 192; idx += NTHREADS) {
            int e = idx / 192, k = idx % 192;
            int n = nbase + e;
            float v = 0.f;
            if (n < NN) {
                if (k < 128) {
                    float a = g_A[(u64)n * FEAT + k];
                    v = a * a;
                } else {
                    int m = k - 128;
                    const float* p = &g_A[(u64)n * FEAT + 128 + m * 3];
                    float q0 = p[0], q1 = p[1], q2 = p[2];
                    v = (q0 * q0 + q1 * q1 + q2 * q2) * 0.5773502691896258f;
                }
            }
            b2f[((e >> 1) * 192 + k) * 2 + (e & 1)] = v;
        }
        __syncthreads();

        // ---- copy A1 to out, zero scratch cols 128..319 ----
        for (int idx = tid; idx < TN * 192; idx += NTHREADS) {
            int e = idx / 192, k = idx % 192;
            int n = nbase + e;
            if (n < NN) {
                u64 off = (u64)n * FEAT + 128 + k;
                out[off] = g_A[off];
                g_A[off] = 0.f;
            }
        }

        // ---- mix0 = B0 @ Wmix0' (thread owns cols 4cg..4cg+3) ----
        u64 acc[2][4];
#pragma unroll
        for (int p = 0; p < 2; p++)
#pragma unroll
            for (int c = 0; c < 4; c++) acc[p][c] = 0ull;
#pragma unroll 2
        for (int k = 0; k < 192; k++) {
            u64 a[2];
#pragma unroll
            for (int p = 0; p < 2; p++)
                a[p] = *(const u64*)&b2f[((eg * 2 + p) * 192 + k) * 2];
            float4 w4 = *(const float4*)&Wm[k * 128 + 4 * cg];
            u64 wd0 = pack2(w4.x, w4.x);
            u64 wd1 = pack2(w4.y, w4.y);
            u64 wd2 = pack2(w4.z, w4.z);
            u64 wd3 = pack2(w4.w, w4.w);
#pragma unroll
            for (int p = 0; p < 2; p++) {
                fma2(acc[p][0], a[p], wd0);
                fma2(acc[p][1], a[p], wd1);
                fma2(acc[p][2], a[p], wd2);
                fma2(acc[p][3], a[p], wd3);
            }
        }

        // ---- out[:, :128] = A0 + mix0; zero scratch cols 0..127 ----
#pragma unroll
        for (int p = 0; p < 2; p++) {
            int n0 = nbase + (eg * 2 + p) * 2;
            int n1 = n0 + 1;
            float a0, b0, a1, b1, a2, b2, a3, b3;
            unpack2(acc[p][0], a0, b0);
            unpack2(acc[p][1], a1, b1);
            unpack2(acc[p][2], a2, b2);
            unpack2(acc[p][3], a3, b3);
            if (n0 < NN) {
                u64 off = (u64)n0 * FEAT + 4 * cg;
                float4 A0 = *(const float4*)&g_A[off];
                *(float4*)&out[off] = make_float4(A0.x + a0, A0.y + a1, A0.z + a2, A0.w + a3);
                *(float4*)&g_A[off] = make_float4(0.f, 0.f, 0.f, 0.f);
            }
            if (n1 < NN) {
                u64 off = (u64)n1 * FEAT + 4 * cg;
                float4 A0 = *(const float4*)&g_A[off];
                *(float4*)&out[off] = make_float4(A0.x + b0, A0.y + b1, A0.z + b2, A0.w + b3);
                *(float4*)&g_A[off] = make_float4(0.f, 0.f, 0.f, 0.f);
            }
        }
        __syncthreads();
    }

    // ---- reset barrier counters (last block out) ----
    __syncthreads();
    if (tid == 0) {
        __threadfence();
        unsigned d = atomicAdd(&g_depart, 1u);
        if (d == (unsigned)gridDim.x - 1) {
            g_arrive = 0;
            g_depart = 0;
            __threadfence();
        }
    }
}

extern "C" void kernel_launch(void* const* d_in, const int* in_sizes, int n_in,
                              void* d_out, int out_size) {
    const float* node_attrs = (const float*)d_in[0];
    const int*   edge_index = (const int*)d_in[1];
    const float* edge_vec   = (const float*)d_in[2];
    const float* edge_len   = (const float*)d_in[3];
    const float* W1         = (const float*)d_in[4];
    const float* W2         = (const float*)d_in[5];
    const float* Wtp0       = (const float*)d_in[6];
    const float* Wtp1       = (const float*)d_in[7];
    const float* Wmix0      = (const float*)d_in[8];
    float* out = (float*)d_out;

    cudaFuncSetAttribute(ace_fused_kernel, cudaFuncAttributeMaxDynamicSharedMemorySize, SMEM_BYTES);

    ace_fused_kernel<<<NBLOCKS, NTHREADS, SMEM_BYTES>>>(
        node_attrs, edge_index, edge_vec, edge_len, W1, W2, Wtp0, Wtp1, Wmix0, out);
}